// round 16
// baseline (speedup 1.0000x reference)
#include <cuda_runtime.h>
#include <math.h>
#include <stdint.h>

// ---------------- problem constants ----------------
#define NPIX   1024          // 32*32
#define C_MID  512
#define KTOT   2304          // 256*9
#define KSPLIT 9
#define KPER   (KTOT / KSPLIT)   // 256
#define NBOX   9216          // 1024*9
#define NW     144           // NBOX/64
#define IOU_THR 0.7f
#define NBLK   144           // persistent grid size (<= 148 SMs, 1 wave)

// ---------------- static device scratch ----------------
__device__ float g_wt[KTOT * C_MID];                 // conv1 weights transposed [k][co]
__device__ float g_col[KTOT * NPIX];                 // im2col [k][p]
__device__ float g_hp[KSPLIT * NPIX * C_MID];        // split-K partial activations
__device__ float g_boxes[NBOX * 4];
__device__ float g_scores[NBOX];
__device__ __align__(16) unsigned long long g_key[NBOX];
__device__ int g_order[NBOX];
__device__ float4 g_bsorted[NBOX];
__device__ unsigned long long g_mask[(size_t)NBOX * NW];
__device__ unsigned long long g_keepmask[NW];
__device__ int g_V;
__device__ int g_barcnt;
__device__ volatile int g_bargen;

// anchors: a = size_idx*3 + ratio_idx, sizes {32,64,128}, ratios {.5,1,2}
__constant__ float c_aw[9] = {
    45.254833995939045f, 32.0f, 22.627416997969522f,
    90.50966799187809f,  64.0f, 45.254833995939045f,
    181.01933598375618f, 128.0f, 90.50966799187809f };
__constant__ float c_ah[9] = {
    22.627416997969522f, 32.0f, 45.254833995939045f,
    45.254833995939045f, 64.0f, 90.50966799187809f,
    90.50966799187809f,  128.0f, 181.01933598375618f };

// ---------------- packed f32x2 helpers (sm_103a) ----------------
__device__ __forceinline__ void ffma2(unsigned long long& acc, unsigned long long a, unsigned long long b) {
    asm("fma.rn.f32x2 %0, %1, %2, %0;" : "+l"(acc) : "l"(a), "l"(b));
}
__device__ __forceinline__ unsigned long long dup2(float x) {
    unsigned long long r;
    asm("mov.b64 %0, {%1, %1};" : "=l"(r) : "f"(x));
    return r;
}
__device__ __forceinline__ void unpack2(unsigned long long v, float& lo, float& hi) {
    asm("mov.b64 {%0, %1}, %2;" : "=f"(lo), "=f"(hi) : "l"(v));
}

// ---------------- grid barrier (all NBLK blocks resident) ----------------
__device__ __forceinline__ void gsync() {
    __syncthreads();
    if (threadIdx.x == 0) {
        __threadfence();
        int gen = g_bargen;
        if (atomicAdd(&g_barcnt, 1) == NBLK - 1) {
            g_barcnt = 0;
            __threadfence();
            g_bargen = gen + 1;
        } else {
            while (g_bargen == gen) { }
        }
        __threadfence();
    }
    __syncthreads();
}

// ---------------- K0: prep: weight transpose + im2col + reset ----------------
#define TBLK 1152                    // (2304/32)*(512/32)
__global__ void __launch_bounds__(256) k_prep(const float* __restrict__ w, const float* __restrict__ feat) {
    const int bid = blockIdx.x;
    const int t = threadIdx.x;
    if (bid < TBLK) {                           // transpose w1 [512][2304] -> g_wt [2304][512]
        __shared__ float tile[32][33];
        int kb = (bid % 72) * 32, cb = (bid / 72) * 32;
        int tx = t & 31, ty = t >> 5;
        for (int i = ty; i < 32; i += 8)
            tile[i][tx] = w[(cb + i) * KTOT + kb + tx];
        __syncthreads();
        for (int i = ty; i < 32; i += 8)
            g_wt[(kb + i) * C_MID + cb + tx] = tile[tx][i];
    } else if (bid < TBLK + 9216) {             // im2col
        int e = (bid - TBLK) * 256 + t;
        int k = e >> 10, p = e & 1023;
        int c = k / 9, tt = k - c * 9;
        int y = (p >> 5) + tt / 3 - 1;
        int x = (p & 31) + tt % 3 - 1;
        float v = 0.0f;
        if ((unsigned)y < 32u && (unsigned)x < 32u) v = feat[c * NPIX + y * 32 + x];
        g_col[e] = v;
    } else {                                    // reset counters (graph replay determinism)
        if (t == 0) { g_V = 0; g_barcnt = 0; g_bargen = 0; }
    }
}

// ================ persistent mega-kernel: all post-prep phases ================
__global__ void __launch_bounds__(256, 1) k_main(const float* __restrict__ b1,
                                                 const float* __restrict__ w2, const float* __restrict__ b2,
                                                 const float* __restrict__ w3, const float* __restrict__ b3,
                                                 float* __restrict__ out) {
    __shared__ __align__(16) char smu[49152];   // phase-reused union (48 KB)
    const int bid = blockIdx.x;
    const int t = threadIdx.x;

    // ---------------- phase A: SGEMM 1024x512x2304, split-K x9, f32x2 ----------------
    {
        float (*As)[256] = (float (*)[256])smu;                 // 32 KB
        float (*Bs)[128] = (float (*)[128])(smu + 32768);       // 16 KB
        const int tx = t & 15;                // co group (8 co)
        const int ty = t >> 4;                // pixel group (16 px)
        const int co0 = (bid & 3) * 128;
        const int p0  = ((bid >> 2) & 3) * 256;
        const int kz  = bid >> 4;             // 0..8

        unsigned long long acc[16][4];
#pragma unroll
        for (int i = 0; i < 16; i++)
#pragma unroll
            for (int j = 0; j < 4; j++) acc[i][j] = 0ull;

        const int kbeg = kz * KPER;
        for (int k0 = kbeg; k0 < kbeg + KPER; k0 += 32) {
#pragma unroll
            for (int i = 0; i < 8; i++) {
                int idx = t + i * 256;
                int kk = idx >> 6, q = idx & 63;
                *(float4*)&As[kk][q * 4] = *(const float4*)&g_col[(size_t)(k0 + kk) * NPIX + p0 + q * 4];
            }
#pragma unroll
            for (int i = 0; i < 4; i++) {
                int idx = t + i * 256;
                int kk = idx >> 5, q = idx & 31;
                *(float4*)&Bs[kk][q * 4] = *(const float4*)&g_wt[(size_t)(k0 + kk) * C_MID + co0 + q * 4];
            }
            __syncthreads();
#pragma unroll
            for (int kk = 0; kk < 32; kk++) {
                float4 a0 = *(const float4*)&As[kk][ty * 16];
                float4 a1 = *(const float4*)&As[kk][ty * 16 + 4];
                float4 a2 = *(const float4*)&As[kk][ty * 16 + 8];
                float4 a3 = *(const float4*)&As[kk][ty * 16 + 12];
                ulonglong2 bq = *(const ulonglong2*)&Bs[kk][tx * 8];
                ulonglong2 br = *(const ulonglong2*)&Bs[kk][tx * 8 + 4];
                float av[16] = {a0.x, a0.y, a0.z, a0.w, a1.x, a1.y, a1.z, a1.w,
                                a2.x, a2.y, a2.z, a2.w, a3.x, a3.y, a3.z, a3.w};
#pragma unroll
                for (int i = 0; i < 16; i++) {
                    unsigned long long ai = dup2(av[i]);
                    ffma2(acc[i][0], ai, bq.x);
                    ffma2(acc[i][1], ai, bq.y);
                    ffma2(acc[i][2], ai, br.x);
                    ffma2(acc[i][3], ai, br.y);
                }
            }
            __syncthreads();
        }
        float* outb = &g_hp[(size_t)kz * NPIX * C_MID];
#pragma unroll
        for (int i = 0; i < 16; i++) {
            int p = p0 + ty * 16 + i;
            float v[8];
#pragma unroll
            for (int j = 0; j < 4; j++) unpack2(acc[i][j], v[2 * j], v[2 * j + 1]);
            float* dst = &outb[(size_t)p * C_MID + co0 + tx * 8];
            *(float4*)dst       = make_float4(v[0], v[1], v[2], v[3]);
            *(float4*)(dst + 4) = make_float4(v[4], v[5], v[6], v[7]);
        }
    }
    gsync();

    // ---------------- phase B: combine + bias + relu, heads, decode, keys ----------------
    if (bid < 128) {
        float (*hsm)[512] = (float (*)[512])smu;                  // 16 KB
        float (*res)[48]  = (float (*)[48])(smu + 16384);         // 1.5 KB
        int* bcnt = (int*)(smu + 17920);
        const int p0 = bid * 8;
        const int lane = t & 31, warp = t >> 5;
        if (t == 0) *bcnt = 0;

        for (int e = t; e < 8 * 128; e += 256) {
            int px = e >> 7, cq = e & 127;
            size_t off = (size_t)(p0 + px) * C_MID + cq * 4;
            float4 s = *(const float4*)&g_hp[off];
#pragma unroll
            for (int sk = 1; sk < KSPLIT; sk++) {
                float4 q = *(const float4*)&g_hp[(size_t)sk * NPIX * C_MID + off];
                s.x += q.x; s.y += q.y; s.z += q.z; s.w += q.w;
            }
            float4 bb = *(const float4*)&b1[cq * 4];
            hsm[px][cq * 4 + 0] = fmaxf(s.x + bb.x, 0.0f);
            hsm[px][cq * 4 + 1] = fmaxf(s.y + bb.y, 0.0f);
            hsm[px][cq * 4 + 2] = fmaxf(s.z + bb.z, 0.0f);
            hsm[px][cq * 4 + 3] = fmaxf(s.w + bb.w, 0.0f);
        }
        __syncthreads();

        for (int o = warp; o < 45; o += 8) {
            const float* wr; float bv;
            if (o < 9) { wr = w2 + o * 512; bv = b2[o]; }
            else       { wr = w3 + (o - 9) * 512; bv = b3[o - 9]; }
            float acc[8] = {0, 0, 0, 0, 0, 0, 0, 0};
#pragma unroll 4
            for (int c = lane; c < 512; c += 32) {
                float wv = wr[c];
#pragma unroll
                for (int px = 0; px < 8; px++) acc[px] += hsm[px][c] * wv;
            }
#pragma unroll
            for (int px = 0; px < 8; px++) {
#pragma unroll
                for (int s = 16; s; s >>= 1) acc[px] += __shfl_xor_sync(0xffffffffu, acc[px], s);
                if (lane == 0) res[px][o] = acc[px] + bv;
            }
        }
        __syncthreads();

        if (t < 72) {
            const int pxl = t / 9, a = t % 9;
            const int p = p0 + pxl;
            float logit = res[pxl][a];
            float score = 1.0f / (1.0f + expf(-logit));
            float o0 = res[pxl][9 + a * 4 + 0];
            float o1 = res[pxl][9 + a * 4 + 1];
            float o2 = res[pxl][9 + a * 4 + 2];
            float o3 = res[pxl][9 + a * 4 + 3];
            int y = p >> 5, x = p & 31;
            float acx = ((float)x + 0.5f) * 16.0f;
            float acy = ((float)y + 0.5f) * 16.0f;
            float aw = c_aw[a], ah = c_ah[a];
            float cx = acx + o0 * aw;
            float cy = acy + o1 * ah;
            float bw = aw * expf(o2);
            float bh = ah * expf(o3);
            float x1 = fminf(fmaxf(cx - bw * 0.5f, 0.0f), 512.0f);
            float y1 = fminf(fmaxf(cy - bh * 0.5f, 0.0f), 512.0f);
            float x2 = fminf(fmaxf(cx + bw * 0.5f, 0.0f), 512.0f);
            float y2 = fminf(fmaxf(cy + bh * 0.5f, 0.0f), 512.0f);
            bool valid = (x2 - x1 >= 0.001f) && (y2 - y1 >= 0.001f) && (score >= 0.5f);
            int i = p * 9 + a;
            g_boxes[i * 4 + 0] = x1;
            g_boxes[i * 4 + 1] = y1;
            g_boxes[i * 4 + 2] = x2;
            g_boxes[i * 4 + 3] = y2;
            g_scores[i] = score;
            if (valid) atomicAdd(bcnt, 1);
            float seff = valid ? score : -INFINITY;
            unsigned int b = __float_as_uint(seff);
            unsigned int u = (b & 0x80000000u) ? ~b : (b | 0x80000000u);
            unsigned int d = ~u;
            g_key[i] = ((unsigned long long)d << 32) | (unsigned int)i;
        }
        __syncthreads();
        if (t == 0 && *bcnt) atomicAdd(&g_V, *bcnt);
    }
    gsync();

    // ---------------- phase C: rank (block-local) + scatter ----------------
    {
        ulonglong2* sT = (ulonglong2*)smu;              // 512 entries, 8 KB
        int* rsum = (int*)(smu + 8192);                 // 64 ints
        const int il = t & 63;                          // item local
        const int seg = t >> 6;                         // 0..3 key segments
        const int item = bid * 64 + il;
        const unsigned long long ki = g_key[item];
        const ulonglong2* kk2 = (const ulonglong2*)g_key;
        int cnt = 0;
        if (t < 64) rsum[t] = 0;
        for (int step = 0; step < 9; step++) {
            __syncthreads();
            {
                int i1 = t, i2 = t + 256;
                sT[i1] = kk2[(i1 >> 7) * 1152 + step * 128 + (i1 & 127)];
                sT[i2] = kk2[(i2 >> 7) * 1152 + step * 128 + (i2 & 127)];
            }
            __syncthreads();
            const int sb = seg * 128;
#pragma unroll 8
            for (int j = 0; j < 128; j++) {
                ulonglong2 v = sT[sb + j];
                cnt += (v.x < ki) ? 1 : 0;
                cnt += (v.y < ki) ? 1 : 0;
            }
        }
        __syncthreads();
        atomicAdd(&rsum[il], cnt);
        __syncthreads();
        if (t < 64) {
            int r = rsum[t];
            int it2 = bid * 64 + t;
            g_order[r] = it2;
            g_bsorted[r] = *(const float4*)&g_boxes[it2 * 4];
        }
    }
    gsync();

    // ---------------- phase D: pairwise IoU bitmask ----------------
    {
        const int V = g_V;
        const int NC = (V + 63) >> 6;
        const int rc = bid;
        if (rc < NC) {
            float4 (*cb)[64] = (float4 (*)[64])smu;     // 4 KB
            const int wl = t >> 6;
            const int rl = t & 63;
            const int i = rc * 64 + rl;
            float4 bi = (i < V) ? g_bsorted[i] : make_float4(0, 0, 0, 0);
            float areai = (bi.z - bi.x) * (bi.w - bi.y);
            const int ng = NC - rc;
            const int nu = (ng + 3) >> 2;
            for (int u = 0; u < nu; u++) {
                int s = u * 4 + wl;
                int cc = rc + s;
                bool act = (s < ng);
                __syncthreads();
                if (act) cb[wl][rl] = g_bsorted[cc * 64 + rl];
                __syncthreads();
                if (act && i < V) {
                    unsigned long long bits = 0;
                    int jmax = min(64, V - cc * 64);
                    for (int jj = 0; jj < jmax; jj++) {
                        int j = cc * 64 + jj;
                        float4 bj = cb[wl][jj];
                        float ix1 = fmaxf(bi.x, bj.x);
                        float iy1 = fmaxf(bi.y, bj.y);
                        float ix2 = fminf(bi.z, bj.z);
                        float iy2 = fminf(bi.w, bj.w);
                        float inter = fmaxf(ix2 - ix1, 0.0f) * fmaxf(iy2 - iy1, 0.0f);
                        float uni = areai + (bj.z - bj.x) * (bj.w - bj.y) - inter;
                        float iou = inter / fmaxf(uni, 1e-9f);
                        unsigned long long hit = (iou > IOU_THR && j > i) ? 1ull : 0ull;
                        bits |= hit << jj;
                    }
                    g_mask[(size_t)i * NW + cc] = bits;
                }
            }
        }
    }
    gsync();

    // ---------------- phase E: serial greedy NMS (block 0) ----------------
    if (bid == 0) {
        unsigned long long* supp  = (unsigned long long*)smu;            // 1152 B
        unsigned long long* keepm = (unsigned long long*)(smu + 1152);   // 1152 B
        unsigned long long (*dbuf)[64] = (unsigned long long (*)[64])(smu + 2304); // 1 KB
        unsigned long long* s_km = (unsigned long long*)(smu + 3328);
        for (int w = t; w < NW; w += 256) { supp[w] = 0ull; keepm[w] = 0ull; }
        const int V = g_V;
        const int NC = (V + 63) >> 6;
        if (t < 64) dbuf[0][t] = (t < V) ? g_mask[(size_t)t * NW + 0] : 0ull;
        __syncthreads();
        for (int c = 0; c < NC; c++) {
            if (t == 0) {
                const unsigned long long* rb = dbuf[c & 1];
                unsigned long long cur = supp[c], km = 0ull;
#pragma unroll
                for (int b = 0; b < 64; b++) {
                    unsigned long long keep = (~cur >> b) & 1ull;
                    km |= keep << b;
                    cur |= rb[b] & (0ull - keep);
                }
                keepm[c] = km;
                *s_km = km;
            }
            __syncthreads();
            const unsigned long long km = *s_km;
            if (t >= 64 && t < 128) {
                int b = t - 64, nc1 = c + 1;
                if (nc1 < NC) {
                    int row = nc1 * 64 + b;
                    dbuf[nc1 & 1][b] = (row < V) ? g_mask[(size_t)row * NW + nc1] : 0ull;
                }
            }
            const unsigned long long* rowbase = &g_mask[(size_t)(c * 64) * NW];
            for (int w = c + 1 + t; w < NC; w += 256) {
                unsigned long long acc = 0ull;
#pragma unroll
                for (int b = 0; b < 64; b++) {
                    unsigned long long m = 0ull - ((km >> b) & 1ull);
                    acc |= rowbase[(size_t)b * NW + w] & m;
                }
                supp[w] |= acc;
            }
            __syncthreads();
        }
        for (int w = t; w < NW; w += 256) g_keepmask[w] = keepm[w];
    }
    gsync();

    // ---------------- phase F: write output ----------------
    if (t < 64) {
        int p = bid * 64 + t;                      // sorted position
        int V = g_V;
        bool keep = (p < V) && ((g_keepmask[p >> 6] >> (p & 63)) & 1ull);
        int orig = g_order[p];
        float4 b = *(const float4*)&g_boxes[orig * 4];
        float s = g_scores[orig];
        float k = keep ? 1.0f : 0.0f;
        out[orig * 5 + 0] = b.x * k;
        out[orig * 5 + 1] = b.y * k;
        out[orig * 5 + 2] = b.z * k;
        out[orig * 5 + 3] = b.w * k;
        out[orig * 5 + 4] = s * k;
    }
}

// ---------------- host launcher ----------------
extern "C" void kernel_launch(void* const* d_in, const int* in_sizes, int n_in,
                              void* d_out, int out_size) {
    const float* feat = (const float*)d_in[0];
    const float* w1   = (const float*)d_in[1];
    const float* b1   = (const float*)d_in[2];
    const float* w2   = (const float*)d_in[3];
    const float* b2   = (const float*)d_in[4];
    const float* w3   = (const float*)d_in[5];
    const float* b3   = (const float*)d_in[6];
    float* out = (float*)d_out;

    k_prep<<<TBLK + 9216 + 1, 256>>>(w1, feat);
    k_main<<<NBLK, 256>>>(b1, w2, b2, w3, b3, out);
}